// round 1
// baseline (speedup 1.0000x reference)
#include <cuda_runtime.h>

// MutilBlockExtractor: k=3 block-expanded flow warp + mask + group-sum.
// out[b,c,yo,xo] = sum_{n=0..3} m(batch,cell) * bilinear_zero(source[batch,c], py, px)
//   batch = n*4 + b, cell = (yo/3, xo/3), py = ysrc + (yo%3-1) + fy, px analogous.
// Key identity: within a cell all 9 outputs share frac(py),frac(px) ->
// 4x4 patch + separable 2-tap filter (16 loads, 51 FMAs for 9 outputs).

namespace {
constexpr int B      = 4;     // output batch
constexpr int NUMG   = 4;     // groups summed
constexpr int BSZ    = 16;    // total input batches
constexpr int DS     = 256;   // channels
constexpr int HO     = 192, WO = 192;
constexpr int CELLS  = 64 * 64;  // 4096 cells per plane
}

// Per-(batch,cell) precomputed params: {ty, tx, mask, packed(yb,xb)}
__device__ float4 g_pre[BSZ * CELLS];

__global__ void pre_kernel(const float* __restrict__ flow,
                           const float* __restrict__ masks) {
    int idx = blockIdx.x * 256 + threadIdx.x;          // 16*4096 threads
    int batch = idx >> 12;
    int cell  = idx & (CELLS - 1);
    int ysrc = cell >> 6;
    int xsrc = cell & 63;
    float fy = flow[(batch * 2 + 0) * CELLS + cell];
    float fx = flow[(batch * 2 + 1) * CELLS + cell];
    float m  = masks[batch * CELLS + cell];
    float py = (float)ysrc + fy;
    float px = (float)xsrc + fx;
    float fpy = floorf(py), fpx = floorf(px);
    int yb = (int)fpy - 1;                             // patch base row
    int xb = (int)fpx - 1;                             // patch base col
    int packed = (yb & 0xffff) | (xb << 16);
    g_pre[idx] = make_float4(py - fpy, px - fpx, m, __int_as_float(packed));
}

__global__ __launch_bounds__(256) void main_kernel(const float* __restrict__ source,
                                                   float* __restrict__ out) {
    extern __shared__ float s_src[];                   // 4 planes * 4096 floats = 64KB
    const int c   = blockIdx.x;                        // channel
    const int b   = blockIdx.y;                        // output batch
    const int tid = threadIdx.x;

    // Stage the 4 source planes (batch = n*4+b, channel c) into smem.
#pragma unroll
    for (int n = 0; n < NUMG; n++) {
        const float4* src = reinterpret_cast<const float4*>(
            source + (size_t)((n * B + b) * DS + c) * CELLS);
        float4* dst = reinterpret_cast<float4*>(s_src + n * CELLS);
#pragma unroll
        for (int i = 0; i < 4; i++) dst[i * 256 + tid] = src[i * 256 + tid];
    }
    __syncthreads();

    for (int cc = 0; cc < 16; cc++) {
        const int cell = cc * 256 + tid;               // warp lanes = consecutive xsrc
        float acc[9];
#pragma unroll
        for (int i = 0; i < 9; i++) acc[i] = 0.f;

#pragma unroll
        for (int n = 0; n < NUMG; n++) {
            const float4 pre = g_pre[(n * B + b) * CELLS + cell];
            const float ty = pre.x, tx = pre.y, m = pre.z;
            const int packed = __float_as_int(pre.w);
            const int yb = (int)(short)(packed & 0xffff);
            const int xb = packed >> 16;               // arithmetic shift

            float vy[4], vx[4];
            int ro[4], xc[4];
#pragma unroll
            for (int i = 0; i < 4; i++) {
                int yi = yb + i;
                vy[i] = ((unsigned)yi < 64u) ? 1.f : 0.f;
                ro[i] = (yi & 63) << 6;                // wrap (validity zeroes OOB)
                int xi = xb + i;
                vx[i] = ((unsigned)xi < 64u) ? 1.f : 0.f;
                xc[i] = xi & 63;
            }
            // Validity (zero-padding) folded into the filter taps; mask folded into x-taps.
            float wy0[3], wy1[3], wx0[3], wx1[3];
#pragma unroll
            for (int i = 0; i < 3; i++) {
                wy0[i] = (1.f - ty) * vy[i];
                wy1[i] = ty * vy[i + 1];
                wx0[i] = m * (1.f - tx) * vx[i];
                wx1[i] = m * tx * vx[i + 1];
            }

            const float* sp = s_src + n * CELLS;
            float p[4][4];
#pragma unroll
            for (int i = 0; i < 4; i++)
#pragma unroll
                for (int j = 0; j < 4; j++)
                    p[i][j] = sp[ro[i] + xc[j]];

            float r[3][4];
#pragma unroll
            for (int i = 0; i < 3; i++)
#pragma unroll
                for (int j = 0; j < 4; j++)
                    r[i][j] = wy0[i] * p[i][j] + wy1[i] * p[i + 1][j];

#pragma unroll
            for (int i = 0; i < 3; i++)
#pragma unroll
                for (int kk = 0; kk < 3; kk++)
                    acc[i * 3 + kk] += wx0[kk] * r[i][kk] + wx1[kk] * r[i][kk + 1];
        }

        const int ysrc = cell >> 6, xsrc = cell & 63;
        float* o = out + ((size_t)(b * DS + c) * HO + ysrc * 3) * WO + xsrc * 3;
#pragma unroll
        for (int i = 0; i < 3; i++)
#pragma unroll
            for (int kk = 0; kk < 3; kk++)
                o[i * WO + kk] = acc[i * 3 + kk];
    }
}

extern "C" void kernel_launch(void* const* d_in, const int* in_sizes, int n_in,
                              void* d_out, int out_size) {
    const float* source = (const float*)d_in[0];
    const float* flow   = (const float*)d_in[1];
    const float* masks  = (const float*)d_in[2];
    float* out          = (float*)d_out;

    pre_kernel<<<BSZ * CELLS / 256, 256>>>(flow, masks);

    const int smem = NUMG * CELLS * (int)sizeof(float);  // 65536
    cudaFuncSetAttribute(main_kernel, cudaFuncAttributeMaxDynamicSharedMemorySize, smem);
    dim3 grid(DS, B);
    main_kernel<<<grid, 256, smem>>>(source, out);
}

// round 2
// speedup vs baseline: 1.1406x; 1.1406x over previous
#include <cuda_runtime.h>

// MutilBlockExtractor: k=3 block-expanded flow warp + mask + group-sum.
// out[b,c,yo,xo] = sum_{n=0..3} m(batch,cell) * bilinear_zero(source[batch,c], py, px)
//   batch = n*4 + b, cell = (yo/3, xo/3), py = ysrc + (yo%3-1) + fy, px analogous.
// Within a cell all 9 outputs share frac(py),frac(px) -> 4x4 patch + separable
// 2-tap filter (16 smem loads, ~51 FMAs for 9 outputs).
// R2: 512-thread CTAs (3/SM, 48 warps = 75% occ) to saturate the L1/shared pipe.

namespace {
constexpr int B      = 4;     // output batch
constexpr int NUMG   = 4;     // groups summed
constexpr int BSZ    = 16;    // total input batches
constexpr int DS     = 256;   // channels
constexpr int HO     = 192, WO = 192;
constexpr int CELLS  = 64 * 64;  // 4096 cells per plane
constexpr int THREADS = 512;
constexpr int CPT     = CELLS / THREADS;  // 8 cells per thread
}

// Per-(batch,cell) precomputed params: {ty, tx, mask, packed(yb,xb)}
__device__ float4 g_pre[BSZ * CELLS];

__global__ void pre_kernel(const float* __restrict__ flow,
                           const float* __restrict__ masks) {
    int idx = blockIdx.x * 256 + threadIdx.x;          // 16*4096 threads
    int batch = idx >> 12;
    int cell  = idx & (CELLS - 1);
    int ysrc = cell >> 6;
    int xsrc = cell & 63;
    float fy = flow[(batch * 2 + 0) * CELLS + cell];
    float fx = flow[(batch * 2 + 1) * CELLS + cell];
    float m  = masks[batch * CELLS + cell];
    float py = (float)ysrc + fy;
    float px = (float)xsrc + fx;
    float fpy = floorf(py), fpx = floorf(px);
    int yb = (int)fpy - 1;                             // patch base row
    int xb = (int)fpx - 1;                             // patch base col
    int packed = (yb & 0xffff) | (xb << 16);
    g_pre[idx] = make_float4(py - fpy, px - fpx, m, __int_as_float(packed));
}

__global__ __launch_bounds__(THREADS, 3) void main_kernel(const float* __restrict__ source,
                                                          float* __restrict__ out) {
    extern __shared__ float s_src[];                   // 4 planes * 4096 floats = 64KB
    const int c   = blockIdx.x;                        // channel
    const int b   = blockIdx.y;                        // output batch
    const int tid = threadIdx.x;

    // Stage the 4 source planes (batch = n*4+b, channel c) into smem.
#pragma unroll
    for (int n = 0; n < NUMG; n++) {
        const float4* src = reinterpret_cast<const float4*>(
            source + (size_t)((n * B + b) * DS + c) * CELLS);
        float4* dst = reinterpret_cast<float4*>(s_src + n * CELLS);
#pragma unroll
        for (int i = 0; i < CELLS / 4 / THREADS; i++)  // 2 iters
            dst[i * THREADS + tid] = src[i * THREADS + tid];
    }
    __syncthreads();

    for (int cc = 0; cc < CPT; cc++) {
        const int cell = cc * THREADS + tid;           // warp lanes = consecutive xsrc
        float acc[9];
#pragma unroll
        for (int i = 0; i < 9; i++) acc[i] = 0.f;

#pragma unroll
        for (int n = 0; n < NUMG; n++) {
            const float4 pre = g_pre[(n * B + b) * CELLS + cell];
            const float ty = pre.x, tx = pre.y, m = pre.z;
            const int packed = __float_as_int(pre.w);
            const int yb = (int)(short)(packed & 0xffff);
            const int xb = packed >> 16;               // arithmetic shift

            float vy[4], vx[4];
            int ro[4], xc[4];
#pragma unroll
            for (int i = 0; i < 4; i++) {
                int yi = yb + i;
                vy[i] = ((unsigned)yi < 64u) ? 1.f : 0.f;
                ro[i] = (yi & 63) << 6;                // wrap (validity zeroes OOB)
                int xi = xb + i;
                vx[i] = ((unsigned)xi < 64u) ? 1.f : 0.f;
                xc[i] = xi & 63;
            }
            // Validity (zero-padding) folded into the filter taps; mask into x-taps.
            float wy0[3], wy1[3], wx0[3], wx1[3];
#pragma unroll
            for (int i = 0; i < 3; i++) {
                wy0[i] = (1.f - ty) * vy[i];
                wy1[i] = ty * vy[i + 1];
                wx0[i] = m * (1.f - tx) * vx[i];
                wx1[i] = m * tx * vx[i + 1];
            }

            const float* sp = s_src + n * CELLS;
            float p[4][4];
#pragma unroll
            for (int i = 0; i < 4; i++)
#pragma unroll
                for (int j = 0; j < 4; j++)
                    p[i][j] = sp[ro[i] + xc[j]];

            float r[3][4];
#pragma unroll
            for (int i = 0; i < 3; i++)
#pragma unroll
                for (int j = 0; j < 4; j++)
                    r[i][j] = wy0[i] * p[i][j] + wy1[i] * p[i + 1][j];

#pragma unroll
            for (int i = 0; i < 3; i++)
#pragma unroll
                for (int kk = 0; kk < 3; kk++)
                    acc[i * 3 + kk] += wx0[kk] * r[i][kk] + wx1[kk] * r[i][kk + 1];
        }

        const int ysrc = cell >> 6, xsrc = cell & 63;
        float* o = out + ((size_t)(b * DS + c) * HO + ysrc * 3) * WO + xsrc * 3;
#pragma unroll
        for (int i = 0; i < 3; i++)
#pragma unroll
            for (int kk = 0; kk < 3; kk++)
                o[i * WO + kk] = acc[i * 3 + kk];
    }
}

extern "C" void kernel_launch(void* const* d_in, const int* in_sizes, int n_in,
                              void* d_out, int out_size) {
    const float* source = (const float*)d_in[0];
    const float* flow   = (const float*)d_in[1];
    const float* masks  = (const float*)d_in[2];
    float* out          = (float*)d_out;

    pre_kernel<<<BSZ * CELLS / 256, 256>>>(flow, masks);

    const int smem = NUMG * CELLS * (int)sizeof(float);  // 65536
    cudaFuncSetAttribute(main_kernel, cudaFuncAttributeMaxDynamicSharedMemorySize, smem);
    dim3 grid(DS, B);
    main_kernel<<<grid, THREADS, smem>>>(source, out);
}

// round 3
// speedup vs baseline: 1.6045x; 1.4068x over previous
#include <cuda_runtime.h>
#include <cuda_fp16.h>

// MutilBlockExtractor: k=3 block-expanded flow warp + mask + group-sum.
// Within a cell all 9 outputs share frac(py),frac(px) -> 4x4 patch + separable
// 2-tap filter. R3: fp16 source planes in smem, duplicated at both half-word
// parities with zero-padded rows, so each patch row (4 consecutive values) is
// two aligned LDS.32 (half2) instead of four scalar LDS -> ~2x fewer LDS
// wavefronts. Filter math stays fp32 (only source storage is half-rounded).

namespace {
constexpr int B       = 4;     // output batch
constexpr int NUMG    = 4;     // groups summed
constexpr int BSZ     = 16;    // total input batches
constexpr int DS      = 256;   // channels
constexpr int HO      = 192, WO = 192;
constexpr int CELLS   = 64 * 64;
constexpr int THREADS = 512;
constexpr int CPT     = CELLS / THREADS;   // 8 cells per thread

// Half-unit layout per plane: copyA rows stride 72 (data at +4..+67),
// copyB rows stride 74 (data at +5..+68, i.e. value x stored at 5+x).
constexpr int STRA  = 72;
constexpr int STRB  = 74;
constexpr int OFFB  = 64 * STRA;           // 4608 halves
constexpr int PLANE = OFFB + 64 * STRB;    // 9344 halves per plane
constexpr int SMEM_BYTES = NUMG * PLANE * 2;  // 74752 B
}

// Per-(batch,cell) precomputed params: {ty, tx, mask, packed(yb,xb)}
__device__ float4 g_pre[BSZ * CELLS];

__global__ void pre_kernel(const float* __restrict__ flow,
                           const float* __restrict__ masks) {
    int idx = blockIdx.x * 256 + threadIdx.x;
    int batch = idx >> 12;
    int cell  = idx & (CELLS - 1);
    int ysrc = cell >> 6;
    int xsrc = cell & 63;
    float fy = flow[(batch * 2 + 0) * CELLS + cell];
    float fx = flow[(batch * 2 + 1) * CELLS + cell];
    float m  = masks[batch * CELLS + cell];
    float py = (float)ysrc + fy;
    float px = (float)xsrc + fx;
    float fpy = floorf(py), fpx = floorf(px);
    int yb = (int)fpy - 1;
    int xb = (int)fpx - 1;
    int packed = (yb & 0xffff) | (xb << 16);
    g_pre[idx] = make_float4(py - fpy, px - fpx, m, __int_as_float(packed));
}

__global__ __launch_bounds__(THREADS, 3) void main_kernel(const float* __restrict__ source,
                                                          float* __restrict__ out) {
    extern __shared__ __half2 s_h2[];                 // NUMG*PLANE halves
    const int c   = blockIdx.x;
    const int b   = blockIdx.y;
    const int tid = threadIdx.x;

    // --- Zero the row pads (copyA: halves {0..3,68..71}; copyB: {0..5,68..73};
    //     overlap with data halves is overwritten by the fill below). ---
    {
        const __half2 z = __floats2half2_rn(0.f, 0.f);
        if (tid < 256) {
            int n = tid >> 6, row = tid & 63;
            int base = n * PLANE + row * STRA;        // copyA
            s_h2[(base + 0) >> 1]  = z;
            s_h2[(base + 2) >> 1]  = z;
            s_h2[(base + 68) >> 1] = z;
            s_h2[(base + 70) >> 1] = z;
        } else {
            int t = tid - 256;
            int n = t >> 6, row = t & 63;
            int base = n * PLANE + OFFB + row * STRB; // copyB
            s_h2[(base + 0) >> 1]  = z;
            s_h2[(base + 2) >> 1]  = z;
            s_h2[(base + 4) >> 1]  = z;
            s_h2[(base + 68) >> 1] = z;
            s_h2[(base + 70) >> 1] = z;
            s_h2[(base + 72) >> 1] = z;
        }
    }
    __syncthreads();

    // --- Stage the 4 source planes as half, both parities. ---
#pragma unroll
    for (int n = 0; n < NUMG; n++) {
        const float4* src = reinterpret_cast<const float4*>(
            source + (size_t)((n * B + b) * DS + c) * CELLS);
#pragma unroll
        for (int i = 0; i < 2; i++) {
            int idx = i * THREADS + tid;              // float4 index
            float4 v = src[idx];
            int g   = idx * 4;
            int row = g >> 6;
            int x0  = g & 63;                         // multiple of 4
            __half2 h01 = __floats2half2_rn(v.x, v.y);
            __half2 h23 = __floats2half2_rn(v.z, v.w);
            // copyA: value x at half-addr row*STRA + 4 + x
            int aA = (n * PLANE + row * STRA + 4 + x0) >> 1;
            s_h2[aA]     = h01;
            s_h2[aA + 1] = h23;
            // copyB: value x at half-addr OFFB + row*STRB + 5 + x
            float vm1 = __shfl_up_sync(0xffffffffu, v.w, 1);
            if ((tid & 15) == 0) vm1 = 0.f;           // x0==0 -> x=-1 pad
            int aB = (n * PLANE + OFFB + row * STRB + 4 + x0) >> 1;
            s_h2[aB]     = __floats2half2_rn(vm1, v.x);
            s_h2[aB + 1] = __floats2half2_rn(v.y, v.z);
            if ((tid & 15) == 15)                     // x0==60: write x=63 (+ pad 0)
                s_h2[aB + 2] = __floats2half2_rn(v.w, 0.f);
        }
    }
    __syncthreads();

    for (int cc = 0; cc < CPT; cc++) {
        const int cell = cc * THREADS + tid;          // warp lanes = consecutive xsrc
        float acc[9];
#pragma unroll
        for (int i = 0; i < 9; i++) acc[i] = 0.f;

#pragma unroll
        for (int n = 0; n < NUMG; n++) {
            const float4 pre = g_pre[(n * B + b) * CELLS + cell];
            const float ty = pre.x, tx = pre.y, m = pre.z;
            const int packed = __float_as_int(pre.w);
            const int yb = (int)(short)(packed & 0xffff);
            const int xb = packed >> 16;

            // Window start, clamped (parity-preserving) so all-invalid windows
            // land in the zeroed pads; weights are zero there anyway.
            const int par = xb & 1;
            int cl = xb;
            const int lo = -4 - par, hi = 64 + par;
            cl = (cl < lo) ? lo : cl;
            cl = (cl > hi) ? hi : cl;
            const int strideH = par ? STRB : STRA;
            const int baseH = n * PLANE + (par ? (OFFB + 5) : 4) + cl;

            float p[4][4], vy[4], vx[4];
#pragma unroll
            for (int i = 0; i < 4; i++) {
                int yi = yb + i;
                vy[i] = ((unsigned)yi < 64u) ? 1.f : 0.f;
                int xi = xb + i;
                vx[i] = ((unsigned)xi < 64u) ? 1.f : 0.f;
                int a = (baseH + (yi & 63) * strideH) >> 1;
                __half2 q0 = s_h2[a];
                __half2 q1 = s_h2[a + 1];
                float2 f0 = __half22float2(q0);
                float2 f1 = __half22float2(q1);
                p[i][0] = f0.x; p[i][1] = f0.y; p[i][2] = f1.x; p[i][3] = f1.y;
            }

            float wy0[3], wy1[3], wx0[3], wx1[3];
#pragma unroll
            for (int i = 0; i < 3; i++) {
                wy0[i] = (1.f - ty) * vy[i];
                wy1[i] = ty * vy[i + 1];
                wx0[i] = m * (1.f - tx) * vx[i];
                wx1[i] = m * tx * vx[i + 1];
            }

            float r[3][4];
#pragma unroll
            for (int i = 0; i < 3; i++)
#pragma unroll
                for (int j = 0; j < 4; j++)
                    r[i][j] = wy0[i] * p[i][j] + wy1[i] * p[i + 1][j];

#pragma unroll
            for (int i = 0; i < 3; i++)
#pragma unroll
                for (int kk = 0; kk < 3; kk++)
                    acc[i * 3 + kk] += wx0[kk] * r[i][kk] + wx1[kk] * r[i][kk + 1];
        }

        const int ysrc = cell >> 6, xsrc = cell & 63;
        float* o = out + ((size_t)(b * DS + c) * HO + ysrc * 3) * WO + xsrc * 3;
#pragma unroll
        for (int i = 0; i < 3; i++)
#pragma unroll
            for (int kk = 0; kk < 3; kk++)
                o[i * WO + kk] = acc[i * 3 + kk];
    }
}

extern "C" void kernel_launch(void* const* d_in, const int* in_sizes, int n_in,
                              void* d_out, int out_size) {
    const float* source = (const float*)d_in[0];
    const float* flow   = (const float*)d_in[1];
    const float* masks  = (const float*)d_in[2];
    float* out          = (float*)d_out;

    pre_kernel<<<BSZ * CELLS / 256, 256>>>(flow, masks);

    cudaFuncSetAttribute(main_kernel, cudaFuncAttributeMaxDynamicSharedMemorySize, SMEM_BYTES);
    dim3 grid(DS, B);
    main_kernel<<<grid, THREADS, SMEM_BYTES>>>(source, out);
}

// round 4
// speedup vs baseline: 1.6805x; 1.0473x over previous
#include <cuda_runtime.h>
#include <cuda_fp16.h>

// MutilBlockExtractor R4: zero-padded fp16 planes (x pads + y pad rows) make
// the bilinear weights UNIFORM per (n,cell): all validity/clamp/address logic
// moves to pre_kernel. Runtime per (n,cell): 1 LDG.128 (precomputed params),
// 8 LDS.32 (immediate offsets, uniform row stride), 12 HFMA2-class y-filter
// ops, 12 cvt, 18 FFMA x-filter. Two parity copies keep every 4-tap x-window
// as two aligned half2 loads.

namespace {
constexpr int B       = 4;
constexpr int NUMG    = 4;
constexpr int BSZ     = 16;
constexpr int DS      = 256;
constexpr int HO      = 192, WO = 192;
constexpr int CELLS   = 4096;
constexpr int THREADS = 512;
constexpr int CPT     = CELLS / THREADS;     // 8

// Plane layout (fp16): rows y=-4..66 -> 71 rows, 74 halves (37 h2 words) per
// row. copyA: value x at half 4+x (even window starts); copyB: value x at
// half 5+x (odd starts). Pads (copyA halves 0..3,68..73; copyB 0..4,69..73;
// rows 0..3,68..70) are zero.
constexpr int WPR    = 37;                   // h2 words per row
constexpr int ROWS   = 71;
constexpr int COPYW  = ROWS * WPR;           // 2627 words per copy
constexpr int PLANEW = 2 * COPYW;            // 5254 words per plane
constexpr int SMEM_BYTES = NUMG * PLANEW * 4;  // 84064 B
}

// Per-(batch,cell): {wx0*m, wx1*m, half2(wy0,wy1) bits, smem word index bits}
__device__ float4 g_pre[BSZ * CELLS];

__global__ void pre_kernel(const float* __restrict__ flow,
                           const float* __restrict__ masks) {
    int idx = blockIdx.x * 256 + threadIdx.x;
    int batch = idx >> 12;
    int cell  = idx & (CELLS - 1);
    int ysrc = cell >> 6;
    int xsrc = cell & 63;
    float fy = flow[(batch * 2 + 0) * CELLS + cell];
    float fx = flow[(batch * 2 + 1) * CELLS + cell];
    float m  = masks[batch * CELLS + cell];
    float py = (float)ysrc + fy;
    float px = (float)xsrc + fx;
    float fpy = floorf(py), fpx = floorf(px);
    float ty = py - fpy, tx = px - fpx;
    int yb = (int)fpy - 1;
    int xb = (int)fpx - 1;

    // Clamp: valid taps exist iff yb in [-3,63] / xb in [-3,63]; otherwise
    // send the whole window into the zero pads (parity-preserving for x).
    int ybc = (yb > 63) ? -4 : max(yb, -4);
    int par = xb & 1;
    int lo  = -4 - par;
    int xbc = (xb >= 64 + par) ? lo : max(xb, lo);

    int wordIdx = par * COPYW + (ybc + 4) * WPR + (((par ? 5 : 4) + xbc) >> 1);

    __half2 wy = __floats2half2_rn(1.f - ty, ty);
    float4 o;
    o.x = m * (1.f - tx);
    o.y = m * tx;
    o.z = __uint_as_float(*reinterpret_cast<unsigned*>(&wy));
    o.w = __int_as_float(wordIdx);
    g_pre[idx] = o;
}

__global__ __launch_bounds__(THREADS, 2) void main_kernel(const float* __restrict__ source,
                                                          float* __restrict__ out) {
    extern __shared__ __half2 s[];               // NUMG * PLANEW words
    const int c   = blockIdx.x;
    const int b   = blockIdx.y;
    const int tid = threadIdx.x;
    const __half2 zero = __float2half2_rn(0.f);

    // ---- Zero the pads ----
    // Full pad rows {0,1,2,3,68,69,70} for all 8 (plane,copy) pairs.
    for (int i = tid; i < 8 * 7 * WPR; i += THREADS) {
        int w  = i % WPR;
        int t  = i / WPR;
        int r7 = t % 7;
        int pc = t / 7;
        int row = (r7 < 4) ? r7 : (64 + r7);     // 0..3, 68..70
        s[pc * COPYW + row * WPR + w] = zero;
    }
    // Side pads on data rows 4..67: words {0,1,35,36} in both copies.
    for (int i = tid; i < 8 * 64 * 4; i += THREADS) {
        int w4 = i & 3;
        int t  = i >> 2;
        int r  = (t & 63) + 4;
        int pc = t >> 6;
        int w  = (w4 < 2) ? w4 : (33 + w4);      // 0,1,35,36
        s[pc * COPYW + r * WPR + w] = zero;
    }
    // copyA word 34 (halves 68,69 = x pads) on data rows.
    for (int i = tid; i < 4 * 64; i += THREADS) {
        int r = (i & 63) + 4;
        int n = i >> 6;
        s[n * PLANEW + r * WPR + 34] = zero;
    }
    __syncthreads();

    // ---- Stage the 4 source planes as half, both parities ----
#pragma unroll
    for (int n = 0; n < NUMG; n++) {
        const float4* src = reinterpret_cast<const float4*>(
            source + (size_t)((n * B + b) * DS + c) * CELLS);
#pragma unroll
        for (int i = 0; i < 2; i++) {
            int idx = i * THREADS + tid;
            float4 v = src[idx];
            int g  = idx * 4;
            int y  = g >> 6;
            int x0 = g & 63;                     // multiple of 4
            int rw = (y + 4) * WPR + ((4 + x0) >> 1);
            int wA = n * PLANEW + rw;
            s[wA]     = __floats2half2_rn(v.x, v.y);
            s[wA + 1] = __floats2half2_rn(v.z, v.w);
            float vm1 = __shfl_up_sync(0xffffffffu, v.w, 1);
            if ((tid & 15) == 0) vm1 = 0.f;      // x0==0 -> x=-1 pad
            int wB = wA + COPYW;
            s[wB]     = __floats2half2_rn(vm1, v.x);
            s[wB + 1] = __floats2half2_rn(v.y, v.z);
            if ((tid & 15) == 15)                // x0==60: write x=63 + pad 0
                s[wB + 2] = __floats2half2_rn(v.w, 0.f);
        }
    }
    __syncthreads();

    for (int cc = 0; cc < CPT; cc++) {
        const int cell = cc * THREADS + tid;     // warp lanes = consecutive xsrc
        float acc[9];
#pragma unroll
        for (int i = 0; i < 9; i++) acc[i] = 0.f;

#pragma unroll
        for (int n = 0; n < NUMG; n++) {
            const float4 pre = g_pre[(n * B + b) * CELLS + cell];
            const float wx0 = pre.x, wx1 = pre.y;
            unsigned wyb = __float_as_uint(pre.z);
            const int bw = __float_as_int(pre.w);
            const __half2 wyh = *reinterpret_cast<const __half2*>(&wyb);
            const __half2 wy0 = __low2half2(wyh);
            const __half2 wy1 = __high2half2(wyh);

            const __half2* sp = s + n * PLANEW + bw;
            __half2 p0a = sp[0],        p0b = sp[1];
            __half2 p1a = sp[WPR],      p1b = sp[WPR + 1];
            __half2 p2a = sp[2 * WPR],  p2b = sp[2 * WPR + 1];
            __half2 p3a = sp[3 * WPR],  p3b = sp[3 * WPR + 1];

            // y-filter in half2 (uniform weights; pads supply zeros)
            __half2 r0a = __hfma2(wy1, p1a, __hmul2(wy0, p0a));
            __half2 r0b = __hfma2(wy1, p1b, __hmul2(wy0, p0b));
            __half2 r1a = __hfma2(wy1, p2a, __hmul2(wy0, p1a));
            __half2 r1b = __hfma2(wy1, p2b, __hmul2(wy0, p1b));
            __half2 r2a = __hfma2(wy1, p3a, __hmul2(wy0, p2a));
            __half2 r2b = __hfma2(wy1, p3b, __hmul2(wy0, p2b));

            float2 fa, fb;
            fa = __half22float2(r0a); fb = __half22float2(r0b);
            acc[0] = fmaf(wx1, fa.y, fmaf(wx0, fa.x, acc[0]));
            acc[1] = fmaf(wx1, fb.x, fmaf(wx0, fa.y, acc[1]));
            acc[2] = fmaf(wx1, fb.y, fmaf(wx0, fb.x, acc[2]));
            fa = __half22float2(r1a); fb = __half22float2(r1b);
            acc[3] = fmaf(wx1, fa.y, fmaf(wx0, fa.x, acc[3]));
            acc[4] = fmaf(wx1, fb.x, fmaf(wx0, fa.y, acc[4]));
            acc[5] = fmaf(wx1, fb.y, fmaf(wx0, fb.x, acc[5]));
            fa = __half22float2(r2a); fb = __half22float2(r2b);
            acc[6] = fmaf(wx1, fa.y, fmaf(wx0, fa.x, acc[6]));
            acc[7] = fmaf(wx1, fb.x, fmaf(wx0, fa.y, acc[7]));
            acc[8] = fmaf(wx1, fb.y, fmaf(wx0, fb.x, acc[8]));
        }

        const int ysrc = cell >> 6, xsrc = cell & 63;
        float* o = out + ((size_t)(b * DS + c) * HO + ysrc * 3) * WO + xsrc * 3;
#pragma unroll
        for (int i = 0; i < 3; i++)
#pragma unroll
            for (int kk = 0; kk < 3; kk++)
                o[i * WO + kk] = acc[i * 3 + kk];
    }
}

extern "C" void kernel_launch(void* const* d_in, const int* in_sizes, int n_in,
                              void* d_out, int out_size) {
    const float* source = (const float*)d_in[0];
    const float* flow   = (const float*)d_in[1];
    const float* masks  = (const float*)d_in[2];
    float* out          = (float*)d_out;

    pre_kernel<<<BSZ * CELLS / 256, 256>>>(flow, masks);

    cudaFuncSetAttribute(main_kernel, cudaFuncAttributeMaxDynamicSharedMemorySize, SMEM_BYTES);
    dim3 grid(DS, B);
    main_kernel<<<grid, THREADS, SMEM_BYTES>>>(source, out);
}